// round 16
// baseline (speedup 1.0000x reference)
#include <cuda_runtime.h>
#include <cuda_bf16.h>
#include <math.h>
#include <stdint.h>

// Problem dims (fixed by the reference setup)
#define BB 8
#define CC 512
#define LL 2048
#define NG 32
#define CPG 16

static const long long CL  = (long long)CC * LL;      // 1,048,576
static const long long LL2 = (long long)LL * LL;      // 4,194,304

// ---------------- scratch (device globals; no cudaMalloc allowed) ----------
__device__ __nv_bfloat16 g_ht[BB * CC * LL];              // hT [L][C]
__device__ __nv_bfloat16 g_qk[BB * 2 * CC * LL];          // qkT [L][2C]
__device__ __nv_bfloat16 g_v [BB * CC * LL];              // v [C][L]
__device__ __nv_bfloat16 g_h2[BB * CC * LL];              // h2T [L][C]
__device__ float         g_s [(long long)BB * LL * LL];   // scores fp32 [L][L]
__device__ __nv_bfloat16 g_p [(long long)BB * LL * LL];   // softmax P bf16 [L][L]
__device__ __nv_bfloat16 g_wh[4 * CC * CC];               // bf16 wq,wk,wv,wo
__device__ float         g_bc[2 * CC];                    // concat bq,bk

// ---------------- weight bf16 conversion (one launch) ------------------------
__global__ void __launch_bounds__(256)
cvtb_kernel(const float4* __restrict__ a, const float4* __restrict__ b,
            const float4* __restrict__ c, const float4* __restrict__ d,
            __nv_bfloat162* __restrict__ out)
{
    int i = blockIdx.x * 256 + threadIdx.x;       // 0 .. 262143
    int seg = i >> 16, off = i & 65535;
    const float4* src = (seg == 0) ? a : (seg == 1) ? b : (seg == 2) ? c : d;
    float4 v = src[off];
    out[2 * i]     = __nv_bfloat162{__float2bfloat16_rn(v.x), __float2bfloat16_rn(v.y)};
    out[2 * i + 1] = __nv_bfloat162{__float2bfloat16_rn(v.z), __float2bfloat16_rn(v.w)};
}

// ---------------- bias concat (bq|bk) -----------------------------------------
__global__ void __launch_bounds__(256)
bcat_kernel(const float* __restrict__ bq, const float* __restrict__ bk,
            float* __restrict__ out)
{
    int i = blockIdx.x * 256 + threadIdx.x;       // 0..1023
    if (i < CC)          out[i] = bq[i];
    else if (i < 2 * CC) out[i] = bk[i - CC];
}

// ---------------- GroupNorm: x [C][L] -> hT [L][C] bf16 ----------------------
__global__ void __launch_bounds__(256)
gn_kernel(const float* __restrict__ x, const float* __restrict__ gw,
          const float* __restrict__ gb, __nv_bfloat16* __restrict__ ht)
{
    const int blk   = blockIdx.x;
    const int batch = blk >> 5;
    const int g     = blk & 31;
    const float* xp = x + (long long)batch * CC * LL + (long long)g * CPG * LL;
    __nv_bfloat16* hb = ht + (long long)batch * CC * LL;
    const int tid = threadIdx.x;
    const int NEL = CPG * LL;   // 32768

    float s = 0.f, ss = 0.f;
    for (int i = tid; i < NEL; i += 256) {
        float v = xp[i];
        s += v; ss += v * v;
    }
    __shared__ float rs[32], rss[32];
    #pragma unroll
    for (int o = 16; o; o >>= 1) {
        s  += __shfl_xor_sync(0xffffffffu, s,  o);
        ss += __shfl_xor_sync(0xffffffffu, ss, o);
    }
    const int warp = tid >> 5, lane = tid & 31;
    if (!lane) { rs[warp] = s; rss[warp] = ss; }
    __syncthreads();
    if (tid < 32) {
        float s2  = (tid < 8) ? rs[tid]  : 0.f;
        float ss2 = (tid < 8) ? rss[tid] : 0.f;
        #pragma unroll
        for (int o = 4; o; o >>= 1) {
            s2  += __shfl_xor_sync(0xffffffffu, s2,  o);
            ss2 += __shfl_xor_sync(0xffffffffu, ss2, o);
        }
        if (!tid) {
            float mean = s2 / (float)NEL;
            float var  = ss2 / (float)NEL - mean * mean;
            rs[0]  = mean;
            rss[0] = rsqrtf(var + 1e-6f);
        }
    }
    __syncthreads();
    const float mean = rs[0], inv = rss[0];

    // staged transpose: tiles of 16 channels x 64 l
    __shared__ __nv_bfloat16 tile[64][17];
    for (int t0 = 0; t0 < LL; t0 += 64) {
        #pragma unroll
        for (int r = 0; r < 4; r++) {
            const int c_local = (tid >> 6) + r * 4;    // 0..15
            const int l_off   = tid & 63;
            const int c = g * CPG + c_local;
            float val = xp[(long long)c_local * LL + t0 + l_off];
            tile[l_off][c_local] =
                __float2bfloat16_rn((val - mean) * inv * gw[c] + gb[c]);
        }
        __syncthreads();
        #pragma unroll
        for (int r = 0; r < 4; r++) {
            const int idx = r * 256 + tid;
            const int l_off = idx >> 4, c_local = idx & 15;
            hb[(long long)(t0 + l_off) * CC + g * CPG + c_local] = tile[l_off][c_local];
        }
        __syncthreads();
    }
}

// ---------------- bf16 mma.sync GEMM, 128x128 tile, 64x64 warp tile ----------
// 128 threads (2x2 warps), 2 CTAs/SM, 3-stage cp.async, ONE barrier per k-step.
// C[m,n] = alpha * sum_k A[m][k] * B[n][k]  (both operands row-major [rows][K])
//          (+ bias: per-M if !BIASN, per-N if BIASN) (+ res[m*ldc+n], fp32)
#define BM 128
#define BN 128
#define BK 64
#define TSTR 72                 // smem row stride in bf16 (144 B; u32 stride 36)
#define TSZ (128 * TSTR)        // 9216 bf16 per tile
#define STAGE_BF (2 * TSZ)      // A tile + B tile = 18432 bf16 = 36864 B
#define GEMM_SMEM (3 * STAGE_BF * 2)   // 110592 B

__device__ __forceinline__ void cp16(uint32_t dst, const void* src) {
    asm volatile("cp.async.ca.shared.global [%0], [%1], 16;" :: "r"(dst), "l"(src));
}

__device__ __forceinline__ void mma16(float* c, const uint32_t* a, const uint32_t* b) {
    asm volatile(
        "mma.sync.aligned.m16n8k16.row.col.f32.bf16.bf16.f32 "
        "{%0,%1,%2,%3}, {%4,%5,%6,%7}, {%8,%9}, {%0,%1,%2,%3};"
        : "+f"(c[0]), "+f"(c[1]), "+f"(c[2]), "+f"(c[3])
        : "r"(a[0]), "r"(a[1]), "r"(a[2]), "r"(a[3]), "r"(b[0]), "r"(b[1]));
}

__device__ __forceinline__ void store_pair(float* C, long long o, float a, float b) {
    *(float2*)&C[o] = make_float2(a, b);
}
__device__ __forceinline__ void store_pair(__nv_bfloat16* C, long long o, float a, float b) {
    *(__nv_bfloat162*)&C[o] =
        __nv_bfloat162{__float2bfloat16_rn(a), __float2bfloat16_rn(b)};
}

template<bool BIASN, typename TO>
__global__ void __launch_bounds__(128, 2)
gemm_bf16(const __nv_bfloat16* __restrict__ A, long long sA, int lda,
          const __nv_bfloat16* __restrict__ B, long long sB, int ldb,
          const float* __restrict__ bias,
          const float* __restrict__ res, long long sRes,
          TO* __restrict__ C, long long sC, int ldc,
          int K, float alpha)
{
    extern __shared__ __nv_bfloat16 smem_bf[];   // 3 stages x [A | B]

    const int z = blockIdx.z;
    A += (long long)z * sA;
    B += (long long)z * sB;
    C += (long long)z * sC;
    const float* R = res ? res + (long long)z * sRes : nullptr;

    const int bm = blockIdx.y * BM;
    const int bn = blockIdx.x * BN;
    const int tid  = threadIdx.x;          // 0..127
    const int warp = tid >> 5, lane = tid & 31;
    const int wm = warp >> 1, wn = warp & 1;   // 2x2 warp grid, 64x64 each
    const int g  = lane >> 2, t  = lane & 3;

    const uint32_t sm_u = (uint32_t)__cvta_generic_to_shared(smem_bf);

    float acc[4][8][4];
    #pragma unroll
    for (int i = 0; i < 4; i++)
        #pragma unroll
        for (int j = 0; j < 8; j++)
            #pragma unroll
            for (int q = 0; q < 4; q++) acc[i][j][q] = 0.f;

    // fill: conflict-free octets — bank-quad = 4*(row+kq) mod 32; within each
    // lane-octet rows are 8 consecutive (kq fixed) -> distinct quads.
    const int r8  = lane & 7;
    const int kql = lane >> 3;             // 0..3
    auto fill = [&](int stg, int k0) {
        const uint32_t ab = sm_u + (uint32_t)(stg * STAGE_BF * 2);
        const uint32_t bb = ab + (uint32_t)(TSZ * 2);
        #pragma unroll
        for (int half = 0; half < 2; half++) {
            const int kq = kql + 4 * half;
            #pragma unroll
            for (int i = 0; i < 4; i++) {
                const int row = r8 + 8 * warp + 32 * i;
                cp16(ab + (uint32_t)(row * 144 + kq * 16),
                     A + (long long)(bm + row) * lda + k0 + kq * 8);
                cp16(bb + (uint32_t)(row * 144 + kq * 16),
                     B + (long long)(bn + row) * ldb + k0 + kq * 8);
            }
        }
        asm volatile("cp.async.commit_group;" ::: "memory");
    };

    const int nk = K / BK;        // >= 8 for all our GEMMs
    fill(0, 0);
    fill(1, BK);

    int cur = 0, nxt = 2;
    for (int ks = 0; ks < nk; ks++) {
        if (ks + 2 < nk) asm volatile("cp.async.wait_group 1;" ::: "memory");
        else             asm volatile("cp.async.wait_group 0;" ::: "memory");
        __syncthreads();
        // fill the stage computed last iteration (all warps passed the barrier)
        if (ks + 2 < nk) {
            fill(nxt, (ks + 2) * BK);
            nxt = (nxt == 2) ? 0 : nxt + 1;
        }

        const uint32_t* Ab = (const uint32_t*)(smem_bf + cur * STAGE_BF);
        const uint32_t* Bb = (const uint32_t*)(smem_bf + cur * STAGE_BF + TSZ);

        #pragma unroll
        for (int kh = 0; kh < 4; kh++) {       // 4 x k16
            uint32_t bfr[8][2];
            #pragma unroll
            for (int nt = 0; nt < 8; nt++) {
                const int o = (wn * 64 + nt * 8 + g) * 36 + kh * 8 + t;
                bfr[nt][0] = Bb[o];
                bfr[nt][1] = Bb[o + 4];
            }
            #pragma unroll
            for (int mt = 0; mt < 4; mt++) {
                const int o = (wm * 64 + mt * 16 + g) * 36 + kh * 8 + t;
                uint32_t af[4];
                af[0] = Ab[o];        af[1] = Ab[o + 288];
                af[2] = Ab[o + 4];    af[3] = Ab[o + 292];
                #pragma unroll
                for (int nt = 0; nt < 8; nt++)
                    mma16(acc[mt][nt], af, bfr[nt]);
            }
        }
        cur = (cur == 2) ? 0 : cur + 1;
    }

    // epilogue: c0:(g,2t) c1:(g,2t+1) c2:(g+8,2t) c3:(g+8,2t+1)
    #pragma unroll
    for (int mt = 0; mt < 4; mt++) {
        const int r0 = bm + wm * 64 + mt * 16 + g;
        float bm0 = 0.f, bm1 = 0.f;
        if (!BIASN && bias) { bm0 = bias[r0]; bm1 = bias[r0 + 8]; }
        #pragma unroll
        for (int nt = 0; nt < 8; nt++) {
            const int c0 = bn + wn * 64 + nt * 8 + 2 * t;
            float v00 = acc[mt][nt][0] * alpha + bm0;
            float v01 = acc[mt][nt][1] * alpha + bm0;
            float v10 = acc[mt][nt][2] * alpha + bm1;
            float v11 = acc[mt][nt][3] * alpha + bm1;
            if (BIASN && bias) {
                const float bn0 = bias[c0], bn1 = bias[c0 + 1];
                v00 += bn0; v01 += bn1; v10 += bn0; v11 += bn1;
            }
            if (R) {
                const float2 r0v = *(const float2*)&R[(long long)r0 * ldc + c0];
                const float2 r1v = *(const float2*)&R[(long long)(r0 + 8) * ldc + c0];
                v00 += r0v.x; v01 += r0v.y;
                v10 += r1v.x; v11 += r1v.y;
            }
            store_pair(C, (long long)r0 * ldc + c0, v00, v01);
            store_pair(C, (long long)(r0 + 8) * ldc + c0, v10, v11);
        }
    }
}

// ---------------- row softmax: fp32 S -> bf16 P (vectorized) -------------------
__global__ void __launch_bounds__(256)
softmax_kernel(const float* __restrict__ sm, __nv_bfloat16* __restrict__ pm)
{
    const float4* row = (const float4*)(sm + (long long)blockIdx.x * LL);
    __nv_bfloat162* prow = (__nv_bfloat162*)(pm + (long long)blockIdx.x * LL);
    const int tid = threadIdx.x;
    const int warp = tid >> 5, lane = tid & 31;

    float4 va = row[tid];
    float4 vb = row[tid + 256];
    float mx = fmaxf(fmaxf(fmaxf(va.x, va.y), fmaxf(va.z, va.w)),
                     fmaxf(fmaxf(vb.x, vb.y), fmaxf(vb.z, vb.w)));

    __shared__ float red[32];
    __shared__ float bcast;
    #pragma unroll
    for (int o = 16; o; o >>= 1) mx = fmaxf(mx, __shfl_xor_sync(0xffffffffu, mx, o));
    if (!lane) red[warp] = mx;
    __syncthreads();
    if (tid < 32) {
        float m2 = (tid < 8) ? red[tid] : -1e30f;
        #pragma unroll
        for (int o = 4; o; o >>= 1) m2 = fmaxf(m2, __shfl_xor_sync(0xffffffffu, m2, o));
        if (!tid) bcast = m2;
    }
    __syncthreads();
    mx = bcast;

    va.x = expf(va.x - mx); va.y = expf(va.y - mx);
    va.z = expf(va.z - mx); va.w = expf(va.w - mx);
    vb.x = expf(vb.x - mx); vb.y = expf(vb.y - mx);
    vb.z = expf(vb.z - mx); vb.w = expf(vb.w - mx);
    float s = va.x + va.y + va.z + va.w + vb.x + vb.y + vb.z + vb.w;

    #pragma unroll
    for (int o = 16; o; o >>= 1) s += __shfl_xor_sync(0xffffffffu, s, o);
    if (!lane) red[warp] = s;
    __syncthreads();
    if (tid < 32) {
        float s2 = (tid < 8) ? red[tid] : 0.f;
        #pragma unroll
        for (int o = 4; o; o >>= 1) s2 += __shfl_xor_sync(0xffffffffu, s2, o);
        if (!tid) bcast = s2;
    }
    __syncthreads();
    const float inv = 1.f / bcast;

    prow[2 * tid] = __nv_bfloat162{__float2bfloat16_rn(va.x * inv),
                                   __float2bfloat16_rn(va.y * inv)};
    prow[2 * tid + 1] = __nv_bfloat162{__float2bfloat16_rn(va.z * inv),
                                       __float2bfloat16_rn(va.w * inv)};
    prow[2 * (tid + 256)] = __nv_bfloat162{__float2bfloat16_rn(vb.x * inv),
                                           __float2bfloat16_rn(vb.y * inv)};
    prow[2 * (tid + 256) + 1] = __nv_bfloat162{__float2bfloat16_rn(vb.z * inv),
                                               __float2bfloat16_rn(vb.w * inv)};
}

// ---------------- launch ------------------------------------------------------
extern "C" void kernel_launch(void* const* d_in, const int* in_sizes, int n_in,
                              void* d_out, int out_size)
{
    const float* x  = (const float*)d_in[0];
    const float* gw = (const float*)d_in[1];
    const float* gb = (const float*)d_in[2];
    const float* wq = (const float*)d_in[3];
    const float* bq = (const float*)d_in[4];
    const float* wk = (const float*)d_in[5];
    const float* bk = (const float*)d_in[6];
    const float* wv = (const float*)d_in[7];
    const float* bv = (const float*)d_in[8];
    const float* wo = (const float*)d_in[9];
    const float* bo = (const float*)d_in[10];
    float* out = (float*)d_out;

    __nv_bfloat16 *ht, *qk, *v, *h2, *p, *wh;
    float *s, *bc;
    cudaGetSymbolAddress((void**)&ht, g_ht);
    cudaGetSymbolAddress((void**)&qk, g_qk);
    cudaGetSymbolAddress((void**)&v,  g_v);
    cudaGetSymbolAddress((void**)&h2, g_h2);
    cudaGetSymbolAddress((void**)&s,  g_s);
    cudaGetSymbolAddress((void**)&p,  g_p);
    cudaGetSymbolAddress((void**)&wh, g_wh);
    cudaGetSymbolAddress((void**)&bc, g_bc);

    __nv_bfloat16* wqk = wh;                    // [2C][C]: wq rows then wk rows
    __nv_bfloat16* wvh = wh + 2 * CC * CC;      // [C][C]
    __nv_bfloat16* woh = wh + 3 * CC * CC;      // [C][C]

    cudaFuncSetAttribute(gemm_bf16<true, __nv_bfloat16>,
                         cudaFuncAttributeMaxDynamicSharedMemorySize, GEMM_SMEM);
    cudaFuncSetAttribute(gemm_bf16<false, __nv_bfloat16>,
                         cudaFuncAttributeMaxDynamicSharedMemorySize, GEMM_SMEM);
    cudaFuncSetAttribute(gemm_bf16<false, float>,
                         cudaFuncAttributeMaxDynamicSharedMemorySize, GEMM_SMEM);

    const float scale = 0.044194173824159216f;   // 512^-0.5
    dim3 blk(128);

    // 0) bf16 weights + bias concat
    cvtb_kernel<<<1024, 256>>>((const float4*)wq, (const float4*)wk,
                               (const float4*)wv, (const float4*)wo,
                               (__nv_bfloat162*)wh);
    bcat_kernel<<<4, 256>>>(bq, bk, bc);

    // 1) GroupNorm -> hT [L][C] bf16
    gn_kernel<<<BB * NG, 256>>>(x, gw, gb, ht);

    // 2) qkT[L][2C] = hT @ wqk^T + (bq|bk)   (M=L, N=2C, K=C)
    gemm_bf16<true, __nv_bfloat16><<<dim3(2 * CC / BN, LL / BM, BB), blk, GEMM_SMEM>>>(
        ht, CL, CC, wqk, 0LL, CC, bc, nullptr, 0LL,
        qk, 2 * CL, 2 * CC, CC, 1.f);

    // 3) v[C][L] = wv @ h + bv   (M=C, N=L, K=C; B = hT [L][C])
    gemm_bf16<false, __nv_bfloat16><<<dim3(LL / BN, CC / BM, BB), blk, GEMM_SMEM>>>(
        wvh, 0LL, CC, ht, CL, CC, bv, nullptr, 0LL,
        v, CL, LL, CC, 1.f);

    // 4) S = scale * q @ k^T   (M=L, N=L, K=C; A = qkT[:, :C], B = qkT[:, C:])
    gemm_bf16<false, float><<<dim3(LL / BN, LL / BM, BB), blk, GEMM_SMEM>>>(
        qk, 2 * CL, 2 * CC, qk + CC, 2 * CL, 2 * CC, nullptr, nullptr, 0LL,
        s, LL2, LL, CC, scale);

    // 5) row softmax: S fp32 -> P bf16
    softmax_kernel<<<BB * LL, 256>>>(s, p);

    // 6) h2T[L][C] = P @ v^T   (M=L, N=C, K=L; B = v [C][L])
    gemm_bf16<false, __nv_bfloat16><<<dim3(CC / BN, LL / BM, BB), blk, GEMM_SMEM>>>(
        p, LL2, LL, v, CL, LL, nullptr, nullptr, 0LL,
        h2, CL, CC, LL, 1.f);

    // 7) out = x + wo @ h2 + bo   (M=C, N=L, K=C; B = h2T [L][C])
    gemm_bf16<false, float><<<dim3(LL / BN, CC / BM, BB), blk, GEMM_SMEM>>>(
        woh, 0LL, CC, h2, CL, CC, bo, x, CL,
        out, CL, LL, CC, 1.f);
}

// round 17
// speedup vs baseline: 1.6694x; 1.6694x over previous
#include <cuda_runtime.h>
#include <cuda_bf16.h>
#include <math.h>
#include <stdint.h>

// Problem dims (fixed by the reference setup)
#define BB 8
#define CC 512
#define LL 2048
#define NG 32
#define CPG 16

static const long long CL  = (long long)CC * LL;      // 1,048,576
static const long long LL2 = (long long)LL * LL;      // 4,194,304

// ---------------- scratch (device globals; no cudaMalloc allowed) ----------
__device__ __nv_bfloat16 g_ht[BB * CC * LL];              // hT [L][C]
__device__ __nv_bfloat16 g_qk[BB * 2 * CC * LL];          // qkT [L][2C]
__device__ __nv_bfloat16 g_v [BB * CC * LL];              // v [C][L]
__device__ __nv_bfloat16 g_h2[BB * CC * LL];              // h2T [L][C]
__device__ float         g_s [(long long)BB * LL * LL];   // scores fp32 [L][L]
__device__ __nv_bfloat16 g_p [(long long)BB * LL * LL];   // softmax P bf16 [L][L]
__device__ __nv_bfloat16 g_wh[4 * CC * CC];               // bf16 wq,wk,wv,wo
__device__ float         g_bc[2 * CC];                    // concat bq,bk

// ---------------- weight bf16 conversion (one launch) ------------------------
__global__ void __launch_bounds__(256)
cvtb_kernel(const float4* __restrict__ a, const float4* __restrict__ b,
            const float4* __restrict__ c, const float4* __restrict__ d,
            __nv_bfloat162* __restrict__ out)
{
    int i = blockIdx.x * 256 + threadIdx.x;       // 0 .. 262143
    int seg = i >> 16, off = i & 65535;
    const float4* src = (seg == 0) ? a : (seg == 1) ? b : (seg == 2) ? c : d;
    float4 v = src[off];
    out[2 * i]     = __nv_bfloat162{__float2bfloat16_rn(v.x), __float2bfloat16_rn(v.y)};
    out[2 * i + 1] = __nv_bfloat162{__float2bfloat16_rn(v.z), __float2bfloat16_rn(v.w)};
}

// ---------------- bias concat (bq|bk) -----------------------------------------
__global__ void __launch_bounds__(256)
bcat_kernel(const float* __restrict__ bq, const float* __restrict__ bk,
            float* __restrict__ out)
{
    int i = blockIdx.x * 256 + threadIdx.x;       // 0..1023
    if (i < CC)          out[i] = bq[i];
    else if (i < 2 * CC) out[i] = bk[i - CC];
}

// ---------------- GroupNorm: x [C][L] -> hT [L][C] bf16 ----------------------
__global__ void __launch_bounds__(256)
gn_kernel(const float* __restrict__ x, const float* __restrict__ gw,
          const float* __restrict__ gb, __nv_bfloat16* __restrict__ ht)
{
    const int blk   = blockIdx.x;
    const int batch = blk >> 5;
    const int g     = blk & 31;
    const float* xp = x + (long long)batch * CC * LL + (long long)g * CPG * LL;
    __nv_bfloat16* hb = ht + (long long)batch * CC * LL;
    const int tid = threadIdx.x;
    const int NEL = CPG * LL;   // 32768

    float s = 0.f, ss = 0.f;
    for (int i = tid; i < NEL; i += 256) {
        float v = xp[i];
        s += v; ss += v * v;
    }
    __shared__ float rs[32], rss[32];
    #pragma unroll
    for (int o = 16; o; o >>= 1) {
        s  += __shfl_xor_sync(0xffffffffu, s,  o);
        ss += __shfl_xor_sync(0xffffffffu, ss, o);
    }
    const int warp = tid >> 5, lane = tid & 31;
    if (!lane) { rs[warp] = s; rss[warp] = ss; }
    __syncthreads();
    if (tid < 32) {
        float s2  = (tid < 8) ? rs[tid]  : 0.f;
        float ss2 = (tid < 8) ? rss[tid] : 0.f;
        #pragma unroll
        for (int o = 4; o; o >>= 1) {
            s2  += __shfl_xor_sync(0xffffffffu, s2,  o);
            ss2 += __shfl_xor_sync(0xffffffffu, ss2, o);
        }
        if (!tid) {
            float mean = s2 / (float)NEL;
            float var  = ss2 / (float)NEL - mean * mean;
            rs[0]  = mean;
            rss[0] = rsqrtf(var + 1e-6f);
        }
    }
    __syncthreads();
    const float mean = rs[0], inv = rss[0];

    // staged transpose: tiles of 16 channels x 64 l
    __shared__ __nv_bfloat16 tile[64][17];
    for (int t0 = 0; t0 < LL; t0 += 64) {
        #pragma unroll
        for (int r = 0; r < 4; r++) {
            const int c_local = (tid >> 6) + r * 4;    // 0..15
            const int l_off   = tid & 63;
            const int c = g * CPG + c_local;
            float val = xp[(long long)c_local * LL + t0 + l_off];
            tile[l_off][c_local] =
                __float2bfloat16_rn((val - mean) * inv * gw[c] + gb[c]);
        }
        __syncthreads();
        #pragma unroll
        for (int r = 0; r < 4; r++) {
            const int idx = r * 256 + tid;
            const int l_off = idx >> 4, c_local = idx & 15;
            hb[(long long)(t0 + l_off) * CC + g * CPG + c_local] = tile[l_off][c_local];
        }
        __syncthreads();
    }
}

// ---------------- bf16 mma.sync GEMM, 128x128 tile, 64x64 warp tile ----------
// 128 threads (2x2 warps), 2 CTAs/SM, static smem 40KB, 2-stage cp.async.
// C[m,n] = alpha * sum_k A[m][k] * B[n][k]  (both operands row-major [rows][K])
//          (+ bias: per-M if !BIASN, per-N if BIASN) (+ res[m*ldc+n], fp32)
#define BM 128
#define BN 128
#define BK 32
#define TSTR 40      // smem row stride in bf16 (20 u32)
#define TSZ (128 * TSTR)   // 5120 bf16 per tile buffer

__device__ __forceinline__ void cp16(uint32_t dst, const void* src) {
    asm volatile("cp.async.ca.shared.global [%0], [%1], 16;" :: "r"(dst), "l"(src));
}

__device__ __forceinline__ void mma16(float* c, const uint32_t* a, const uint32_t* b) {
    asm volatile(
        "mma.sync.aligned.m16n8k16.row.col.f32.bf16.bf16.f32 "
        "{%0,%1,%2,%3}, {%4,%5,%6,%7}, {%8,%9}, {%0,%1,%2,%3};"
        : "+f"(c[0]), "+f"(c[1]), "+f"(c[2]), "+f"(c[3])
        : "r"(a[0]), "r"(a[1]), "r"(a[2]), "r"(a[3]), "r"(b[0]), "r"(b[1]));
}

__device__ __forceinline__ void store_pair(float* C, long long o, float a, float b) {
    *(float2*)&C[o] = make_float2(a, b);
}
__device__ __forceinline__ void store_pair(__nv_bfloat16* C, long long o, float a, float b) {
    *(__nv_bfloat162*)&C[o] =
        __nv_bfloat162{__float2bfloat16_rn(a), __float2bfloat16_rn(b)};
}

template<bool BIASN, typename TO>
__global__ void __launch_bounds__(128, 2)
gemm_bf16(const __nv_bfloat16* __restrict__ A, long long sA, int lda,
          const __nv_bfloat16* __restrict__ B, long long sB, int ldb,
          const float* __restrict__ bias,
          const float* __restrict__ res, long long sRes,
          TO* __restrict__ C, long long sC, int ldc,
          int K, float alpha)
{
    __shared__ __nv_bfloat16 As[2][TSZ];
    __shared__ __nv_bfloat16 Bs[2][TSZ];

    const int z = blockIdx.z;
    A += (long long)z * sA;
    B += (long long)z * sB;
    C += (long long)z * sC;
    const float* R = res ? res + (long long)z * sRes : nullptr;

    const int bm = blockIdx.y * BM;
    const int bn = blockIdx.x * BN;
    const int tid  = threadIdx.x;          // 0..127
    const int warp = tid >> 5, lane = tid & 31;
    const int wm = warp >> 1, wn = warp & 1;   // 2x2 warp grid, 64x64 each
    const int g  = lane >> 2, t  = lane & 3;

    const uint32_t as_u = (uint32_t)__cvta_generic_to_shared(&As[0][0]);
    const uint32_t bs_u = (uint32_t)__cvta_generic_to_shared(&Bs[0][0]);

    float acc[4][8][4];
    #pragma unroll
    for (int i = 0; i < 4; i++)
        #pragma unroll
        for (int j = 0; j < 8; j++)
            #pragma unroll
            for (int q = 0; q < 4; q++) acc[i][j][q] = 0.f;

    // fill: both tiles are [128 rows][32 k] bf16, 16B chunks of 8 bf16
    const int kq = tid & 3, r0f = tid >> 2;     // 4 k-quads, 32 rows per pass
    auto fill = [&](int buf, int k0) {
        const uint32_t ab = as_u + (uint32_t)(buf * TSZ * 2);
        const uint32_t bb = bs_u + (uint32_t)(buf * TSZ * 2);
        #pragma unroll
        for (int i = 0; i < 4; i++) {
            const int row = r0f + 32 * i;
            cp16(ab + (uint32_t)(row * (TSTR * 2) + kq * 16),
                 A + (long long)(bm + row) * lda + k0 + kq * 8);
        }
        #pragma unroll
        for (int i = 0; i < 4; i++) {
            const int row = r0f + 32 * i;
            cp16(bb + (uint32_t)(row * (TSTR * 2) + kq * 16),
                 B + (long long)(bn + row) * ldb + k0 + kq * 8);
        }
        asm volatile("cp.async.commit_group;" ::: "memory");
    };

    const int nk = K / BK;
    fill(0, 0);
    int buf = 0;

    for (int ks = 0; ks < nk; ks++) {
        if (ks + 1 < nk) {
            fill(buf ^ 1, (ks + 1) * BK);
            asm volatile("cp.async.wait_group 1;" ::: "memory");
        } else {
            asm volatile("cp.async.wait_group 0;" ::: "memory");
        }
        __syncthreads();

        const uint32_t* Ab = (const uint32_t*)&As[buf][0];
        const uint32_t* Bb = (const uint32_t*)&Bs[buf][0];

        // frag loads: u32 index = row*20 + kh*8 + t (pairs along k)
        auto ldA = [&](uint32_t* af, int kh, int mt) {
            const int o = (wm * 64 + mt * 16 + g) * 20 + kh * 8 + t;
            af[0] = Ab[o];       af[1] = Ab[o + 160];
            af[2] = Ab[o + 4];   af[3] = Ab[o + 164];
        };
        auto ldB = [&](uint32_t* bfr, int kh, int nt) {
            const int o = (wn * 64 + nt * 8 + g) * 20 + kh * 8 + t;
            bfr[0] = Bb[o];      bfr[1] = Bb[o + 4];
        };

        uint32_t af[2][4][4], bfr[2][8][2];
        #pragma unroll
        for (int nt = 0; nt < 8; nt++) ldB(bfr[0][nt], 0, nt);
        #pragma unroll
        for (int mt = 0; mt < 4; mt++) ldA(af[0][mt], 0, mt);

        #pragma unroll
        for (int kh = 0; kh < 2; kh++) {
            const int c = kh & 1, nx = c ^ 1;
            if (kh == 0) {
                #pragma unroll
                for (int nt = 0; nt < 8; nt++) ldB(bfr[nx][nt], 1, nt);
                #pragma unroll
                for (int mt = 0; mt < 4; mt++) ldA(af[nx][mt], 1, mt);
            }
            #pragma unroll
            for (int mt = 0; mt < 4; mt++)
                #pragma unroll
                for (int nt = 0; nt < 8; nt++)
                    mma16(acc[mt][nt], af[c][mt], bfr[c][nt]);
        }
        __syncthreads();
        buf ^= 1;
    }

    // epilogue: c0:(g,2t) c1:(g,2t+1) c2:(g+8,2t) c3:(g+8,2t+1)
    #pragma unroll
    for (int mt = 0; mt < 4; mt++) {
        const int r0 = bm + wm * 64 + mt * 16 + g;
        float bm0 = 0.f, bm1 = 0.f;
        if (!BIASN && bias) { bm0 = bias[r0]; bm1 = bias[r0 + 8]; }
        #pragma unroll
        for (int nt = 0; nt < 8; nt++) {
            const int c0 = bn + wn * 64 + nt * 8 + 2 * t;
            float v00 = acc[mt][nt][0] * alpha + bm0;
            float v01 = acc[mt][nt][1] * alpha + bm0;
            float v10 = acc[mt][nt][2] * alpha + bm1;
            float v11 = acc[mt][nt][3] * alpha + bm1;
            if (BIASN && bias) {
                const float bn0 = bias[c0], bn1 = bias[c0 + 1];
                v00 += bn0; v01 += bn1; v10 += bn0; v11 += bn1;
            }
            if (R) {
                const float2 r0v = *(const float2*)&R[(long long)r0 * ldc + c0];
                const float2 r1v = *(const float2*)&R[(long long)(r0 + 8) * ldc + c0];
                v00 += r0v.x; v01 += r0v.y;
                v10 += r1v.x; v11 += r1v.y;
            }
            store_pair(C, (long long)r0 * ldc + c0, v00, v01);
            store_pair(C, (long long)(r0 + 8) * ldc + c0, v10, v11);
        }
    }
}

// ---------------- row softmax: fp32 S -> bf16 P (vectorized) -------------------
__global__ void __launch_bounds__(256)
softmax_kernel(const float* __restrict__ sm, __nv_bfloat16* __restrict__ pm)
{
    const float4* row = (const float4*)(sm + (long long)blockIdx.x * LL);
    __nv_bfloat162* prow = (__nv_bfloat162*)(pm + (long long)blockIdx.x * LL);
    const int tid = threadIdx.x;
    const int warp = tid >> 5, lane = tid & 31;

    float4 va = row[tid];
    float4 vb = row[tid + 256];
    float mx = fmaxf(fmaxf(fmaxf(va.x, va.y), fmaxf(va.z, va.w)),
                     fmaxf(fmaxf(vb.x, vb.y), fmaxf(vb.z, vb.w)));

    __shared__ float red[32];
    __shared__ float bcast;
    #pragma unroll
    for (int o = 16; o; o >>= 1) mx = fmaxf(mx, __shfl_xor_sync(0xffffffffu, mx, o));
    if (!lane) red[warp] = mx;
    __syncthreads();
    if (tid < 32) {
        float m2 = (tid < 8) ? red[tid] : -1e30f;
        #pragma unroll
        for (int o = 4; o; o >>= 1) m2 = fmaxf(m2, __shfl_xor_sync(0xffffffffu, m2, o));
        if (!tid) bcast = m2;
    }
    __syncthreads();
    mx = bcast;

    va.x = expf(va.x - mx); va.y = expf(va.y - mx);
    va.z = expf(va.z - mx); va.w = expf(va.w - mx);
    vb.x = expf(vb.x - mx); vb.y = expf(vb.y - mx);
    vb.z = expf(vb.z - mx); vb.w = expf(vb.w - mx);
    float s = va.x + va.y + va.z + va.w + vb.x + vb.y + vb.z + vb.w;

    #pragma unroll
    for (int o = 16; o; o >>= 1) s += __shfl_xor_sync(0xffffffffu, s, o);
    if (!lane) red[warp] = s;
    __syncthreads();
    if (tid < 32) {
        float s2 = (tid < 8) ? red[tid] : 0.f;
        #pragma unroll
        for (int o = 4; o; o >>= 1) s2 += __shfl_xor_sync(0xffffffffu, s2, o);
        if (!tid) bcast = s2;
    }
    __syncthreads();
    const float inv = 1.f / bcast;

    prow[2 * tid] = __nv_bfloat162{__float2bfloat16_rn(va.x * inv),
                                   __float2bfloat16_rn(va.y * inv)};
    prow[2 * tid + 1] = __nv_bfloat162{__float2bfloat16_rn(va.z * inv),
                                       __float2bfloat16_rn(va.w * inv)};
    prow[2 * (tid + 256)] = __nv_bfloat162{__float2bfloat16_rn(vb.x * inv),
                                           __float2bfloat16_rn(vb.y * inv)};
    prow[2 * (tid + 256) + 1] = __nv_bfloat162{__float2bfloat16_rn(vb.z * inv),
                                               __float2bfloat16_rn(vb.w * inv)};
}

// ---------------- launch ------------------------------------------------------
extern "C" void kernel_launch(void* const* d_in, const int* in_sizes, int n_in,
                              void* d_out, int out_size)
{
    const float* x  = (const float*)d_in[0];
    const float* gw = (const float*)d_in[1];
    const float* gb = (const float*)d_in[2];
    const float* wq = (const float*)d_in[3];
    const float* bq = (const float*)d_in[4];
    const float* wk = (const float*)d_in[5];
    const float* bk = (const float*)d_in[6];
    const float* wv = (const float*)d_in[7];
    const float* bv = (const float*)d_in[8];
    const float* wo = (const float*)d_in[9];
    const float* bo = (const float*)d_in[10];
    float* out = (float*)d_out;

    __nv_bfloat16 *ht, *qk, *v, *h2, *p, *wh;
    float *s, *bc;
    cudaGetSymbolAddress((void**)&ht, g_ht);
    cudaGetSymbolAddress((void**)&qk, g_qk);
    cudaGetSymbolAddress((void**)&v,  g_v);
    cudaGetSymbolAddress((void**)&h2, g_h2);
    cudaGetSymbolAddress((void**)&s,  g_s);
    cudaGetSymbolAddress((void**)&p,  g_p);
    cudaGetSymbolAddress((void**)&wh, g_wh);
    cudaGetSymbolAddress((void**)&bc, g_bc);

    __nv_bfloat16* wqk = wh;                    // [2C][C]: wq rows then wk rows
    __nv_bfloat16* wvh = wh + 2 * CC * CC;      // [C][C]
    __nv_bfloat16* woh = wh + 3 * CC * CC;      // [C][C]

    const float scale = 0.044194173824159216f;   // 512^-0.5
    dim3 blk(128);

    // 0) bf16 weights + bias concat
    cvtb_kernel<<<1024, 256>>>((const float4*)wq, (const float4*)wk,
                               (const float4*)wv, (const float4*)wo,
                               (__nv_bfloat162*)wh);
    bcat_kernel<<<4, 256>>>(bq, bk, bc);

    // 1) GroupNorm -> hT [L][C] bf16
    gn_kernel<<<BB * NG, 256>>>(x, gw, gb, ht);

    // 2) qkT[L][2C] = hT @ wqk^T + (bq|bk)   (M=L, N=2C, K=C)
    gemm_bf16<true, __nv_bfloat16><<<dim3(2 * CC / BN, LL / BM, BB), blk>>>(
        ht, CL, CC, wqk, 0LL, CC, bc, nullptr, 0LL,
        qk, 2 * CL, 2 * CC, CC, 1.f);

    // 3) v[C][L] = wv @ h + bv   (M=C, N=L, K=C; B = hT [L][C])
    gemm_bf16<false, __nv_bfloat16><<<dim3(LL / BN, CC / BM, BB), blk>>>(
        wvh, 0LL, CC, ht, CL, CC, bv, nullptr, 0LL,
        v, CL, LL, CC, 1.f);

    // 4) S = scale * q @ k^T   (M=L, N=L, K=C; A = qkT[:, :C], B = qkT[:, C:])
    gemm_bf16<false, float><<<dim3(LL / BN, LL / BM, BB), blk>>>(
        qk, 2 * CL, 2 * CC, qk + CC, 2 * CL, 2 * CC, nullptr, nullptr, 0LL,
        s, LL2, LL, CC, scale);

    // 5) row softmax: S fp32 -> P bf16
    softmax_kernel<<<BB * LL, 256>>>(s, p);

    // 6) h2T[L][C] = P @ v^T   (M=L, N=C, K=L; B = v [C][L])
    gemm_bf16<false, __nv_bfloat16><<<dim3(CC / BN, LL / BM, BB), blk>>>(
        p, LL2, LL, v, CL, LL, nullptr, nullptr, 0LL,
        h2, CL, CC, LL, 1.f);

    // 7) out = x + wo @ h2 + bo   (M=C, N=L, K=C; B = h2T [L][C])
    gemm_bf16<false, float><<<dim3(LL / BN, CC / BM, BB), blk>>>(
        woh, 0LL, CC, h2, CL, CC, bo, x, CL,
        out, CL, LL, CC, 1.f);
}